// round 15
// baseline (speedup 1.0000x reference)
#include <cuda_runtime.h>
#include <cuda_bf16.h>

#define NN   20000
#define EE   200000
#define NBLK 3125      /* EE / 64 */

// ---------------- scratch (static device memory; no allocations) ----------------
__device__ float d_h0 [NN*128];
__device__ float d_h1 [NN*128];
__device__ float d_ea1[EE*128];
__device__ float d_z  [EE*128];
__device__ float d_W1T_B[260*128];
__device__ float d_W2T_B[128*128];
__device__ float d_W1T_C[256*128];
__device__ float d_W2T_C[128*128];
__device__ float d_W1T_D[384*128];
__device__ float d_W2T_D[128*128];
__device__ float d_WzT [128*128];
__device__ float d_Mkc [20*128];
__device__ float d_b0v [128];
__device__ float d_wntv[128];
__device__ float d_part [NBLK*128];
__device__ float d_part2[NBLK*128];
__device__ float d_alpha[128];
__device__ float d_beta [128];
__device__ int   d_idx64;

// ---------------- prep: fold conv+mean+fuse into M[20x128]; detect idx dtype ----------------
__global__ void prep_kernel(const float* __restrict__ conv_w, const float* __restrict__ conv_b,
                            const float* __restrict__ emb,
                            const float* __restrict__ fuse_w, const float* __restrict__ fuse_b,
                            const void* __restrict__ eidx)
{
    __shared__ float sA[128][21];   // Aenc[j][k], k = s*4+i (x part only)
    __shared__ float sc0[128];
    int j = threadIdx.x;
    if (j < 128) {
        float c0 = conv_b[j];
        #pragma unroll
        for (int i = 0; i < 8; ++i) {
            float w0 = conv_w[(j*8+i)*3+0];
            float w1 = conv_w[(j*8+i)*3+1];
            float w2 = conv_w[(j*8+i)*3+2];
            #pragma unroll
            for (int s = 0; s < 5; ++s) {
                // Weff[s] = w1 + (w0 if s<=3) + (w2 if s>=1), divided by L=5 for the mean
                float we = w1;
                if (s < 4) we += w0;
                if (s > 0) we += w2;
                we *= 0.2f;
                if (i < 4) sA[j][s*4+i] = we;
                else       c0 += we * emb[s*4 + (i-4)];
            }
        }
        sc0[j] = c0;
    }
    __syncthreads();
    int c = threadIdx.x;
    if (c < 128) {
        const float* fw = fuse_w + c*129;
        for (int k = 0; k < 20; ++k) {
            float m = 0.f;
            #pragma unroll 8
            for (int jj = 0; jj < 128; ++jj) m = fmaf(fw[jj], sA[jj][k], m);
            d_Mkc[k*128 + c] = m;
        }
        float b0 = fuse_b[c];
        #pragma unroll 8
        for (int jj = 0; jj < 128; ++jj) b0 = fmaf(fw[jj], sc0[jj], b0);
        d_b0v[c]  = b0;
        d_wntv[c] = fw[128];
    }
    if (threadIdx.x == 0) {
        // int64 vs int32: int64 node indices (<2^32) have zero high words
        const unsigned long long* p = (const unsigned long long*)eidx;
        int is64 = 1;
        for (int i = 0; i < 64; ++i) if (p[i] >> 32) { is64 = 0; break; }
        d_idx64 = is64;
    }
}

// ---------------- transpose all weight matrices to [K][128] ----------------
__device__ __forceinline__ void do_t(const float* __restrict__ s, float* __restrict__ d, int K)
{
    for (int idx = blockIdx.x*blockDim.x + threadIdx.x; idx < K*128; idx += gridDim.x*blockDim.x)
        d[idx] = s[(idx & 127)*K + (idx >> 7)];
}
__global__ void transpose_all(const float* w1b, const float* w2b,
                              const float* w1c, const float* w2c,
                              const float* w1d, const float* w2d,
                              const float* wz)
{
    do_t(w1b, d_W1T_B, 260);
    do_t(w2b, d_W2T_B, 128);
    do_t(w1c, d_W1T_C, 256);
    do_t(w2c, d_W2T_C, 128);
    do_t(w1d, d_W1T_D, 384);
    do_t(w2d, d_W2T_D, 128);
    do_t(wz,  d_WzT,   128);
}

// ---------------- node features: h0 = M @ xflat + wnt*nt + b0 ----------------
__global__ __launch_bounds__(128) void node_kernel(const float* __restrict__ x,
                                                   const float* __restrict__ nt)
{
    __shared__ float sx[64*20];
    __shared__ float snt[64];
    int c  = threadIdx.x;
    int nb = blockIdx.x * 64;
    int cnt = NN - nb; if (cnt > 64) cnt = 64;
    for (int j = c; j < cnt*20; j += 128) sx[j] = x[nb*20 + j];
    if (c < cnt) snt[c] = nt[nb + c];
    float m[20];
    #pragma unroll
    for (int k = 0; k < 20; ++k) m[k] = d_Mkc[k*128 + c];
    float b0 = d_b0v[c], wnt = d_wntv[c];
    __syncthreads();
    for (int i = 0; i < cnt; ++i) {
        float acc = fmaf(wnt, snt[i], b0);
        #pragma unroll
        for (int k = 0; k < 20; ++k) acc = fmaf(m[k], sx[i*20+k], acc);
        d_h0[(nb+i)*128 + c] = acc;
    }
}

// ---------------- edge-MLP GEMM building blocks ----------------
__device__ __forceinline__ long edge_node(const void* eidx, int idx64, int which, long e)
{
    if (idx64) return (long)((const long long*)eidx)[(long)which*EE + e];
    return (long)((const int*)eidx)[(long)which*EE + e];
}

// one K-segment of GEMM: A(tile in sU) x WT[k0w.., 128] -> acc[4][8]
// W is always a multiple of 4 here (128 or 4).
__device__ __forceinline__ void gemm_seg(float (&A)[4][8], const float* __restrict__ WT,
                                         int k0w, int W,
                                         float (*sU)[132], float (*sB)[128],
                                         int e0l, int oc0)
{
    const int tid = threadIdx.x;
    for (int kb = 0; kb < W; kb += 16) {
        int kw = W - kb; if (kw > 16) kw = 16;
        for (int j = tid; j < (kw << 7); j += 256)
            sB[j >> 7][j & 127] = WT[((k0w + kb + (j >> 7)) << 7) + (j & 127)];
        __syncthreads();
        #pragma unroll 4
        for (int k4 = 0; k4 < kw; k4 += 4) {
            float a4[4][4];
            #pragma unroll
            for (int i = 0; i < 4; ++i)
                *(float4*)a4[i] = *(const float4*)&sU[e0l+i][kb+k4];
            #pragma unroll
            for (int q = 0; q < 4; ++q) {
                const float4 bq0 = *(const float4*)&sB[k4+q][oc0];
                const float4 bq1 = *(const float4*)&sB[k4+q][oc0+4];
                const float bb[8] = {bq0.x,bq0.y,bq0.z,bq0.w,bq1.x,bq1.y,bq1.z,bq1.w};
                #pragma unroll
                for (int i = 0; i < 4; ++i)
                    #pragma unroll
                    for (int j = 0; j < 8; ++j)
                        A[i][j] = fmaf(a4[i][q], bb[j], A[i][j]);
            }
        }
        __syncthreads();
    }
}

// load a 128-wide source segment into sU (gmode 0=gather row, 1=gather col, 2=direct e)
__device__ __forceinline__ void load128(float (*sU)[132], const float* __restrict__ src,
                                        const void* eidx, int idx64, int gmode,
                                        long ebase, int Ecnt)
{
    int r = threadIdx.x >> 2, part = threadIdx.x & 3;
    long e = ebase + r; if (e >= Ecnt) e = Ecnt - 1;
    long gi = (gmode < 2) ? edge_node(eidx, idx64, gmode, e) : e;
    const float4* s = (const float4*)(src + gi*128) + part*8;
    float4* d = (float4*)(&sU[r][part*32]);
    #pragma unroll
    for (int i = 0; i < 8; ++i) d[i] = s[i];
}

// MODE 0: ea1 = MLP([h0[row], h0[col], edge_attr])           (E rows)
// MODE 1: h1  = MLP([h0[row], ea1])                          (N rows only — rest dead)
// MODE 2: ea2 = MLP([h1[row], h1[col], ea1]); z = fm_w1@ea2 + fm_b1; partial BN sums
template<int MODE>
__global__ __launch_bounds__(256) void edge_mlp_kernel(
    const void* __restrict__ eidx, const float* __restrict__ edge_attr,
    const float* __restrict__ b1, const float* __restrict__ b2,
    const float* __restrict__ b3, int Ecnt)
{
    __shared__ float sU[64][132];
    __shared__ float sB[16][128];
    const int tid = threadIdx.x;
    const int oc0 = (tid & 15) * 8;
    const int eg  = tid >> 4;
    const int e0l = eg * 4;
    const long ebase = (long)blockIdx.x * 64;
    const int idx64 = d_idx64;

    const float* W1T = (MODE==0) ? d_W1T_B : (MODE==1) ? d_W1T_C : d_W1T_D;
    const float* W2T = (MODE==0) ? d_W2T_B : (MODE==1) ? d_W2T_C : d_W2T_D;

    float acc[4][8];
    #pragma unroll
    for (int i = 0; i < 4; ++i)
        #pragma unroll
        for (int j = 0; j < 8; ++j) acc[i][j] = 0.f;

    // ---- stage 1 (assembled by source segment) ----
    if (MODE == 0) {
        load128(sU, d_h0, eidx, idx64, 0, ebase, Ecnt); __syncthreads();
        gemm_seg(acc, W1T, 0, 128, sU, sB, e0l, oc0);
        load128(sU, d_h0, eidx, idx64, 1, ebase, Ecnt); __syncthreads();
        gemm_seg(acc, W1T, 128, 128, sU, sB, e0l, oc0);
        { int r = tid >> 2, cc = tid & 3; long e = ebase + r; if (e >= Ecnt) e = Ecnt-1;
          sU[r][cc] = edge_attr[e*4 + cc]; }
        __syncthreads();
        gemm_seg(acc, W1T, 256, 4, sU, sB, e0l, oc0);
    } else if (MODE == 1) {
        load128(sU, d_h0, eidx, idx64, 0, ebase, Ecnt); __syncthreads();
        gemm_seg(acc, W1T, 0, 128, sU, sB, e0l, oc0);
        load128(sU, d_ea1, eidx, idx64, 2, ebase, Ecnt); __syncthreads();
        gemm_seg(acc, W1T, 128, 128, sU, sB, e0l, oc0);
    } else {
        load128(sU, d_h1, eidx, idx64, 0, ebase, Ecnt); __syncthreads();
        gemm_seg(acc, W1T, 0, 128, sU, sB, e0l, oc0);
        load128(sU, d_h1, eidx, idx64, 1, ebase, Ecnt); __syncthreads();
        gemm_seg(acc, W1T, 128, 128, sU, sB, e0l, oc0);
        load128(sU, d_ea1, eidx, idx64, 2, ebase, Ecnt); __syncthreads();
        gemm_seg(acc, W1T, 256, 128, sU, sB, e0l, oc0);
    }

    // ---- stage 1 epilogue: bias + relu -> sU (reuse as H) ----
    {
        float bv[8];
        #pragma unroll
        for (int j = 0; j < 8; ++j) bv[j] = b1[oc0+j];
        #pragma unroll
        for (int i = 0; i < 4; ++i) {
            float4 h0v, h1v;
            h0v.x = fmaxf(acc[i][0]+bv[0], 0.f); h0v.y = fmaxf(acc[i][1]+bv[1], 0.f);
            h0v.z = fmaxf(acc[i][2]+bv[2], 0.f); h0v.w = fmaxf(acc[i][3]+bv[3], 0.f);
            h1v.x = fmaxf(acc[i][4]+bv[4], 0.f); h1v.y = fmaxf(acc[i][5]+bv[5], 0.f);
            h1v.z = fmaxf(acc[i][6]+bv[6], 0.f); h1v.w = fmaxf(acc[i][7]+bv[7], 0.f);
            *(float4*)&sU[e0l+i][oc0]   = h0v;
            *(float4*)&sU[e0l+i][oc0+4] = h1v;
        }
    }
    __syncthreads();

    // ---- stage 2 ----
    float acc2[4][8];
    #pragma unroll
    for (int i = 0; i < 4; ++i)
        #pragma unroll
        for (int j = 0; j < 8; ++j) acc2[i][j] = 0.f;
    gemm_seg(acc2, W2T, 0, 128, sU, sB, e0l, oc0);

    if (MODE != 2) {
        float* out = (MODE == 0) ? d_ea1 : d_h1;
        float bv[8];
        #pragma unroll
        for (int j = 0; j < 8; ++j) bv[j] = b2[oc0+j];
        #pragma unroll
        for (int i = 0; i < 4; ++i) {
            long e = ebase + e0l + i;
            if (e < Ecnt) {
                float4 o0 = {acc2[i][0]+bv[0], acc2[i][1]+bv[1], acc2[i][2]+bv[2], acc2[i][3]+bv[3]};
                float4 o1 = {acc2[i][4]+bv[4], acc2[i][5]+bv[5], acc2[i][6]+bv[6], acc2[i][7]+bv[7]};
                *(float4*)(out + e*128 + oc0)     = o0;
                *(float4*)(out + e*128 + oc0 + 4) = o1;
            }
        }
    } else {
        // ea2 = acc2 + b2 -> sU, then stage 3: z = WzT-gemm + fm_b1
        float bv[8];
        #pragma unroll
        for (int j = 0; j < 8; ++j) bv[j] = b2[oc0+j];
        #pragma unroll
        for (int i = 0; i < 4; ++i) {
            float4 o0 = {acc2[i][0]+bv[0], acc2[i][1]+bv[1], acc2[i][2]+bv[2], acc2[i][3]+bv[3]};
            float4 o1 = {acc2[i][4]+bv[4], acc2[i][5]+bv[5], acc2[i][6]+bv[6], acc2[i][7]+bv[7]};
            *(float4*)&sU[e0l+i][oc0]   = o0;
            *(float4*)&sU[e0l+i][oc0+4] = o1;
        }
        __syncthreads();

        float acc3[4][8];
        #pragma unroll
        for (int i = 0; i < 4; ++i)
            #pragma unroll
            for (int j = 0; j < 8; ++j) acc3[i][j] = 0.f;
        gemm_seg(acc3, d_WzT, 0, 128, sU, sB, e0l, oc0);

        float bz[8];
        #pragma unroll
        for (int j = 0; j < 8; ++j) bz[j] = b3[oc0+j];
        float p[8], p2[8];
        #pragma unroll
        for (int j = 0; j < 8; ++j) { p[j] = 0.f; p2[j] = 0.f; }
        #pragma unroll
        for (int i = 0; i < 4; ++i) {
            long e = ebase + e0l + i;
            if (e < Ecnt) {
                float zv[8];
                #pragma unroll
                for (int j = 0; j < 8; ++j) zv[j] = acc3[i][j] + bz[j];
                float4 z0 = {zv[0],zv[1],zv[2],zv[3]};
                float4 z1 = {zv[4],zv[5],zv[6],zv[7]};
                *(float4*)(d_z + e*128 + oc0)     = z0;
                *(float4*)(d_z + e*128 + oc0 + 4) = z1;
                #pragma unroll
                for (int j = 0; j < 8; ++j) { p[j] += zv[j]; p2[j] = fmaf(zv[j], zv[j], p2[j]); }
            }
        }
        // deterministic per-block reduction via smem scratch (reuse sU)
        float* sp = &sU[0][0];
        #pragma unroll
        for (int j = 0; j < 8; ++j) {
            sp[eg*128 + oc0 + j]        = p[j];
            sp[2048 + eg*128 + oc0 + j] = p2[j];
        }
        __syncthreads();
        if (tid < 128) {
            float s = 0.f, s2 = 0.f;
            #pragma unroll
            for (int g = 0; g < 16; ++g) { s += sp[g*128 + tid]; s2 += sp[2048 + g*128 + tid]; }
            d_part [blockIdx.x*128 + tid] = s;
            d_part2[blockIdx.x*128 + tid] = s2;
        }
    }
}

// ---------------- BN stats (double accumulation; deterministic) ----------------
__global__ void reduce_kernel(const float* __restrict__ bn_g, const float* __restrict__ bn_b)
{
    int c = threadIdx.x;
    if (c >= 128) return;
    double s = 0.0, s2 = 0.0;
    for (int b = 0; b < NBLK; ++b) { s += (double)d_part[b*128+c]; s2 += (double)d_part2[b*128+c]; }
    double mu  = s  / (double)EE;
    double var = s2 / (double)EE - mu*mu;
    float istd = (float)(1.0 / sqrt(var + 1e-5));
    float al = bn_g[c] * istd;
    d_alpha[c] = al;
    d_beta[c]  = bn_b[c] - (float)mu * al;
}

// ---------------- final: out = fm_w2 @ relu(alpha*z + beta) + fm_b2 ----------------
__global__ __launch_bounds__(256) void final_kernel(const float* __restrict__ fm_w2,
                                                    const float* __restrict__ fm_b2,
                                                    float* __restrict__ out)
{
    __shared__ float sw[3*128];
    __shared__ float sa[128], sb[128];
    __shared__ float sbias[3];
    int tid = threadIdx.x;
    for (int t = tid; t < 384; t += 256) sw[t] = fm_w2[t];   // FIX: full 3x128 load
    if (tid < 128) { sa[tid] = d_alpha[tid]; sb[tid] = d_beta[tid]; }
    if (tid < 3)   sbias[tid] = fm_b2[tid];
    __syncthreads();

    int r = tid >> 2, part = tid & 3;
    long e = (long)blockIdx.x * 64 + r;
    long ec = (e < EE) ? e : (EE - 1);
    const float4* zp = (const float4*)(d_z + ec*128) + part*8;
    float a0 = 0.f, a1 = 0.f, a2 = 0.f;
    int base = part * 32;
    #pragma unroll
    for (int i = 0; i < 8; ++i) {
        float4 v = zp[i];
        float vv[4] = {v.x, v.y, v.z, v.w};
        #pragma unroll
        for (int q = 0; q < 4; ++q) {
            int c = base + i*4 + q;
            float zn = fmaxf(fmaf(sa[c], vv[q], sb[c]), 0.f);
            a0 = fmaf(zn, sw[c],       a0);
            a1 = fmaf(zn, sw[128 + c], a1);
            a2 = fmaf(zn, sw[256 + c], a2);
        }
    }
    a0 += __shfl_xor_sync(0xffffffffu, a0, 1); a0 += __shfl_xor_sync(0xffffffffu, a0, 2);
    a1 += __shfl_xor_sync(0xffffffffu, a1, 1); a1 += __shfl_xor_sync(0xffffffffu, a1, 2);
    a2 += __shfl_xor_sync(0xffffffffu, a2, 1); a2 += __shfl_xor_sync(0xffffffffu, a2, 2);
    if (part == 0 && e < EE) {
        out[e*3 + 0] = a0 + sbias[0];
        out[e*3 + 1] = a1 + sbias[1];
        out[e*3 + 2] = a2 + sbias[2];
    }
}

// ---------------- launch ----------------
extern "C" void kernel_launch(void* const* d_in, const int* in_sizes, int n_in,
                              void* d_out, int out_size)
{
    const float* x         = (const float*)d_in[0];
    const void*  eidx      = d_in[1];
    const float* edge_attr = (const float*)d_in[2];
    /* d_in[3] = batch (unused) */
    const float* node_type = (const float*)d_in[4];
    const float* emb       = (const float*)d_in[5];
    const float* conv_w    = (const float*)d_in[6];
    const float* conv_b    = (const float*)d_in[7];
    const float* fuse_w    = (const float*)d_in[8];
    const float* fuse_b    = (const float*)d_in[9];
    const float* g1e_w1    = (const float*)d_in[10];
    const float* g1e_b1    = (const float*)d_in[11];
    const float* g1e_w2    = (const float*)d_in[12];
    const float* g1e_b2    = (const float*)d_in[13];
    const float* g1n_w1    = (const float*)d_in[14];
    const float* g1n_b1    = (const float*)d_in[15];
    const float* g1n_w2    = (const float*)d_in[16];
    const float* g1n_b2    = (const float*)d_in[17];
    const float* g2e_w1    = (const float*)d_in[18];
    const float* g2e_b1    = (const float*)d_in[19];
    const float* g2e_w2    = (const float*)d_in[20];
    const float* g2e_b2    = (const float*)d_in[21];
    /* d_in[22..25] = g2n_* (dead code in reference) */
    const float* fm_w1     = (const float*)d_in[26];
    const float* fm_b1     = (const float*)d_in[27];
    const float* bn_g      = (const float*)d_in[28];
    const float* bn_b      = (const float*)d_in[29];
    const float* fm_w2     = (const float*)d_in[30];
    const float* fm_b2     = (const float*)d_in[31];
    float* out = (float*)d_out;

    prep_kernel<<<1, 128>>>(conv_w, conv_b, emb, fuse_w, fuse_b, eidx);
    transpose_all<<<184, 256>>>(g1e_w1, g1e_w2, g1n_w1, g1n_w2, g2e_w1, g2e_w2, fm_w1);
    node_kernel<<<313, 128>>>(x, node_type);
    edge_mlp_kernel<0><<<NBLK, 256>>>(eidx, edge_attr, g1e_b1, g1e_b2, nullptr, EE);
    edge_mlp_kernel<1><<<313,  256>>>(eidx, edge_attr, g1n_b1, g1n_b2, nullptr, NN);
    edge_mlp_kernel<2><<<NBLK, 256>>>(eidx, edge_attr, g2e_b1, g2e_b2, fm_b1, EE);
    reduce_kernel<<<1, 128>>>(bn_g, bn_b);
    final_kernel<<<NBLK, 256>>>(fm_w2, fm_b2, out);
}

// round 16
// speedup vs baseline: 1.1666x; 1.1666x over previous
#include <cuda_runtime.h>
#include <cuda_bf16.h>

#define NN   20000
#define EE   200000
#define NBLK 3125      /* EE / 64 */

// ---------------- scratch (static device memory; no allocations) ----------------
__device__ float d_h0 [NN*128];
__device__ float d_h1 [NN*128];
__device__ float d_ea1[EE*128];
__device__ float d_z  [EE*128];
__device__ float d_W1T_B[260*128];
__device__ float d_W2T_B[128*128];
__device__ float d_W1T_C[256*128];
__device__ float d_W2T_C[128*128];
__device__ float d_W1T_D[384*128];
__device__ float d_W2T_D[128*128];
__device__ float d_WzT [128*128];
__device__ float d_Mkc [20*128];
__device__ float d_b0v [128];
__device__ float d_wntv[128];
__device__ float d_part [NBLK*128];
__device__ float d_part2[NBLK*128];
__device__ float d_alpha[128];
__device__ float d_beta [128];
__device__ int   d_idx64;

// ---------------- prep: fold conv+mean+fuse into M[20x128]; detect idx dtype ----------------
__global__ void prep_kernel(const float* __restrict__ conv_w, const float* __restrict__ conv_b,
                            const float* __restrict__ emb,
                            const float* __restrict__ fuse_w, const float* __restrict__ fuse_b,
                            const void* __restrict__ eidx)
{
    __shared__ float sA[128][21];
    __shared__ float sc0[128];
    int j = threadIdx.x;
    if (j < 128) {
        float c0 = conv_b[j];
        #pragma unroll
        for (int i = 0; i < 8; ++i) {
            float w0 = conv_w[(j*8+i)*3+0];
            float w1 = conv_w[(j*8+i)*3+1];
            float w2 = conv_w[(j*8+i)*3+2];
            #pragma unroll
            for (int s = 0; s < 5; ++s) {
                float we = w1;
                if (s < 4) we += w0;
                if (s > 0) we += w2;
                we *= 0.2f;
                if (i < 4) sA[j][s*4+i] = we;
                else       c0 += we * emb[s*4 + (i-4)];
            }
        }
        sc0[j] = c0;
    }
    __syncthreads();
    int c = threadIdx.x;
    if (c < 128) {
        const float* fw = fuse_w + c*129;
        for (int k = 0; k < 20; ++k) {
            float m = 0.f;
            #pragma unroll 8
            for (int jj = 0; jj < 128; ++jj) m = fmaf(fw[jj], sA[jj][k], m);
            d_Mkc[k*128 + c] = m;
        }
        float b0 = fuse_b[c];
        #pragma unroll 8
        for (int jj = 0; jj < 128; ++jj) b0 = fmaf(fw[jj], sc0[jj], b0);
        d_b0v[c]  = b0;
        d_wntv[c] = fw[128];
    }
    if (threadIdx.x == 0) {
        const unsigned long long* p = (const unsigned long long*)eidx;
        int is64 = 1;
        for (int i = 0; i < 64; ++i) if (p[i] >> 32) { is64 = 0; break; }
        d_idx64 = is64;
    }
}

// ---------------- transpose all weight matrices to [K][128] ----------------
__device__ __forceinline__ void do_t(const float* __restrict__ s, float* __restrict__ d, int K)
{
    for (int idx = blockIdx.x*blockDim.x + threadIdx.x; idx < K*128; idx += gridDim.x*blockDim.x)
        d[idx] = s[(idx & 127)*K + (idx >> 7)];
}
__global__ void transpose_all(const float* w1b, const float* w2b,
                              const float* w1c, const float* w2c,
                              const float* w1d, const float* w2d,
                              const float* wz)
{
    do_t(w1b, d_W1T_B, 260);
    do_t(w2b, d_W2T_B, 128);
    do_t(w1c, d_W1T_C, 256);
    do_t(w2c, d_W2T_C, 128);
    do_t(w1d, d_W1T_D, 384);
    do_t(w2d, d_W2T_D, 128);
    do_t(wz,  d_WzT,   128);
}

// ---------------- node features: h0 = M @ xflat + wnt*nt + b0 ----------------
__global__ __launch_bounds__(128) void node_kernel(const float* __restrict__ x,
                                                   const float* __restrict__ nt)
{
    __shared__ float sx[64*20];
    __shared__ float snt[64];
    int c  = threadIdx.x;
    int nb = blockIdx.x * 64;
    int cnt = NN - nb; if (cnt > 64) cnt = 64;
    for (int j = c; j < cnt*20; j += 128) sx[j] = x[nb*20 + j];
    if (c < cnt) snt[c] = nt[nb + c];
    float m[20];
    #pragma unroll
    for (int k = 0; k < 20; ++k) m[k] = d_Mkc[k*128 + c];
    float b0 = d_b0v[c], wnt = d_wntv[c];
    __syncthreads();
    for (int i = 0; i < cnt; ++i) {
        float acc = fmaf(wnt, snt[i], b0);
        #pragma unroll
        for (int k = 0; k < 20; ++k) acc = fmaf(m[k], sx[i*20+k], acc);
        d_h0[(nb+i)*128 + c] = acc;
    }
}

// ---------------- edge-MLP GEMM building blocks ----------------
__device__ __forceinline__ long edge_node(const void* eidx, int idx64, int which, long e)
{
    if (idx64) return (long)((const long long*)eidx)[(long)which*EE + e];
    return (long)((const int*)eidx)[(long)which*EE + e];
}

// one K-segment of GEMM: A(64-edge tile in sU) x WT[k0w.., 128] -> acc[8][8]
// 128 threads: colgrp = tid&15 -> oc0, rowgrp = tid>>4 -> e0l (8 rows each).
// W is a multiple of 2 (128 or 4).
__device__ __forceinline__ void gemm_seg(float (&A)[8][8], const float* __restrict__ WT,
                                         int k0w, int W,
                                         float (*sU)[132], float (*sB)[128],
                                         int e0l, int oc0)
{
    const int tid = threadIdx.x;
    for (int kb = 0; kb < W; kb += 16) {
        int kw = W - kb; if (kw > 16) kw = 16;
        for (int j = tid; j < (kw << 7); j += 128)
            sB[j >> 7][j & 127] = WT[((k0w + kb + (j >> 7)) << 7) + (j & 127)];
        __syncthreads();
        #pragma unroll 8
        for (int k2 = 0; k2 < kw; k2 += 2) {
            float2 a2[8];
            #pragma unroll
            for (int i = 0; i < 8; ++i)
                a2[i] = *(const float2*)&sU[e0l+i][kb+k2];
            #pragma unroll
            for (int q = 0; q < 2; ++q) {
                const float4 bq0 = *(const float4*)&sB[k2+q][oc0];
                const float4 bq1 = *(const float4*)&sB[k2+q][oc0+4];
                const float bb[8] = {bq0.x,bq0.y,bq0.z,bq0.w,bq1.x,bq1.y,bq1.z,bq1.w};
                #pragma unroll
                for (int i = 0; i < 8; ++i) {
                    float av = q ? a2[i].y : a2[i].x;
                    #pragma unroll
                    for (int j = 0; j < 8; ++j)
                        A[i][j] = fmaf(av, bb[j], A[i][j]);
                }
            }
        }
        __syncthreads();
    }
}

// load a 128-wide source segment into sU (gmode 0=gather row, 1=gather col, 2=direct e)
// 128 threads, 64 rows -> 2 threads/row, 16 float4 each.
__device__ __forceinline__ void load128(float (*sU)[132], const float* __restrict__ src,
                                        const void* eidx, int idx64, int gmode,
                                        long ebase, int Ecnt)
{
    int r = threadIdx.x >> 1, part = threadIdx.x & 1;
    long e = ebase + r; if (e >= Ecnt) e = Ecnt - 1;
    long gi = (gmode < 2) ? edge_node(eidx, idx64, gmode, e) : e;
    const float4* s = (const float4*)(src + gi*128) + part*16;
    float4* d = (float4*)(&sU[r][part*64]);
    #pragma unroll
    for (int i = 0; i < 16; ++i) d[i] = s[i];
}

// MODE 0: ea1 = MLP([h0[row], h0[col], edge_attr])           (E rows)
// MODE 1: h1  = MLP([h0[row], ea1])                          (N rows only — rest dead)
// MODE 2: ea2 = MLP([h1[row], h1[col], ea1]); z = fm_w1@ea2 + fm_b1; partial BN sums
template<int MODE>
__global__ __launch_bounds__(128) void edge_mlp_kernel(
    const void* __restrict__ eidx, const float* __restrict__ edge_attr,
    const float* __restrict__ b1, const float* __restrict__ b2,
    const float* __restrict__ b3, int Ecnt)
{
    __shared__ float sU[64][132];
    __shared__ float sB[16][128];
    const int tid = threadIdx.x;
    const int oc0 = (tid & 15) * 8;
    const int rg  = tid >> 4;          // 0..7
    const int e0l = rg * 8;
    const long ebase = (long)blockIdx.x * 64;
    const int idx64 = d_idx64;

    const float* W1T = (MODE==0) ? d_W1T_B : (MODE==1) ? d_W1T_C : d_W1T_D;
    const float* W2T = (MODE==0) ? d_W2T_B : (MODE==1) ? d_W2T_C : d_W2T_D;

    float acc[8][8];
    #pragma unroll
    for (int i = 0; i < 8; ++i)
        #pragma unroll
        for (int j = 0; j < 8; ++j) acc[i][j] = 0.f;

    // ---- stage 1 (assembled by source segment) ----
    if (MODE == 0) {
        load128(sU, d_h0, eidx, idx64, 0, ebase, Ecnt); __syncthreads();
        gemm_seg(acc, W1T, 0, 128, sU, sB, e0l, oc0);
        load128(sU, d_h0, eidx, idx64, 1, ebase, Ecnt); __syncthreads();
        gemm_seg(acc, W1T, 128, 128, sU, sB, e0l, oc0);
        for (int idx = tid; idx < 256; idx += 128) {
            int r = idx >> 2, cc = idx & 3;
            long e = ebase + r; if (e >= Ecnt) e = Ecnt-1;
            sU[r][cc] = edge_attr[e*4 + cc];
        }
        __syncthreads();
        gemm_seg(acc, W1T, 256, 4, sU, sB, e0l, oc0);
    } else if (MODE == 1) {
        load128(sU, d_h0, eidx, idx64, 0, ebase, Ecnt); __syncthreads();
        gemm_seg(acc, W1T, 0, 128, sU, sB, e0l, oc0);
        load128(sU, d_ea1, eidx, idx64, 2, ebase, Ecnt); __syncthreads();
        gemm_seg(acc, W1T, 128, 128, sU, sB, e0l, oc0);
    } else {
        load128(sU, d_h1, eidx, idx64, 0, ebase, Ecnt); __syncthreads();
        gemm_seg(acc, W1T, 0, 128, sU, sB, e0l, oc0);
        load128(sU, d_h1, eidx, idx64, 1, ebase, Ecnt); __syncthreads();
        gemm_seg(acc, W1T, 128, 128, sU, sB, e0l, oc0);
        load128(sU, d_ea1, eidx, idx64, 2, ebase, Ecnt); __syncthreads();
        gemm_seg(acc, W1T, 256, 128, sU, sB, e0l, oc0);
    }

    // ---- stage 1 epilogue: bias + relu -> sU (reuse as H) ----
    {
        float bv[8];
        #pragma unroll
        for (int j = 0; j < 8; ++j) bv[j] = b1[oc0+j];
        #pragma unroll
        for (int i = 0; i < 8; ++i) {
            float4 h0v, h1v;
            h0v.x = fmaxf(acc[i][0]+bv[0], 0.f); h0v.y = fmaxf(acc[i][1]+bv[1], 0.f);
            h0v.z = fmaxf(acc[i][2]+bv[2], 0.f); h0v.w = fmaxf(acc[i][3]+bv[3], 0.f);
            h1v.x = fmaxf(acc[i][4]+bv[4], 0.f); h1v.y = fmaxf(acc[i][5]+bv[5], 0.f);
            h1v.z = fmaxf(acc[i][6]+bv[6], 0.f); h1v.w = fmaxf(acc[i][7]+bv[7], 0.f);
            *(float4*)&sU[e0l+i][oc0]   = h0v;
            *(float4*)&sU[e0l+i][oc0+4] = h1v;
        }
    }
    __syncthreads();

    // ---- stage 2 ----
    float acc2[8][8];
    #pragma unroll
    for (int i = 0; i < 8; ++i)
        #pragma unroll
        for (int j = 0; j < 8; ++j) acc2[i][j] = 0.f;
    gemm_seg(acc2, W2T, 0, 128, sU, sB, e0l, oc0);

    if (MODE != 2) {
        float* out = (MODE == 0) ? d_ea1 : d_h1;
        float bv[8];
        #pragma unroll
        for (int j = 0; j < 8; ++j) bv[j] = b2[oc0+j];
        #pragma unroll
        for (int i = 0; i < 8; ++i) {
            long e = ebase + e0l + i;
            if (e < Ecnt) {
                float4 o0 = {acc2[i][0]+bv[0], acc2[i][1]+bv[1], acc2[i][2]+bv[2], acc2[i][3]+bv[3]};
                float4 o1 = {acc2[i][4]+bv[4], acc2[i][5]+bv[5], acc2[i][6]+bv[6], acc2[i][7]+bv[7]};
                *(float4*)(out + e*128 + oc0)     = o0;
                *(float4*)(out + e*128 + oc0 + 4) = o1;
            }
        }
    } else {
        // ea2 = acc2 + b2 -> sU, then stage 3: z = WzT-gemm + fm_b1
        float bv[8];
        #pragma unroll
        for (int j = 0; j < 8; ++j) bv[j] = b2[oc0+j];
        #pragma unroll
        for (int i = 0; i < 8; ++i) {
            float4 o0 = {acc2[i][0]+bv[0], acc2[i][1]+bv[1], acc2[i][2]+bv[2], acc2[i][3]+bv[3]};
            float4 o1 = {acc2[i][4]+bv[4], acc2[i][5]+bv[5], acc2[i][6]+bv[6], acc2[i][7]+bv[7]};
            *(float4*)&sU[e0l+i][oc0]   = o0;
            *(float4*)&sU[e0l+i][oc0+4] = o1;
        }
        __syncthreads();

        float acc3[8][8];
        #pragma unroll
        for (int i = 0; i < 8; ++i)
            #pragma unroll
            for (int j = 0; j < 8; ++j) acc3[i][j] = 0.f;
        gemm_seg(acc3, d_WzT, 0, 128, sU, sB, e0l, oc0);

        float bz[8];
        #pragma unroll
        for (int j = 0; j < 8; ++j) bz[j] = b3[oc0+j];
        float p[8], p2[8];
        #pragma unroll
        for (int j = 0; j < 8; ++j) { p[j] = 0.f; p2[j] = 0.f; }
        #pragma unroll
        for (int i = 0; i < 8; ++i) {
            long e = ebase + e0l + i;
            if (e < Ecnt) {
                float zv[8];
                #pragma unroll
                for (int j = 0; j < 8; ++j) zv[j] = acc3[i][j] + bz[j];
                float4 z0 = {zv[0],zv[1],zv[2],zv[3]};
                float4 z1 = {zv[4],zv[5],zv[6],zv[7]};
                *(float4*)(d_z + e*128 + oc0)     = z0;
                *(float4*)(d_z + e*128 + oc0 + 4) = z1;
                #pragma unroll
                for (int j = 0; j < 8; ++j) { p[j] += zv[j]; p2[j] = fmaf(zv[j], zv[j], p2[j]); }
            }
        }
        // deterministic per-block reduction via smem scratch (reuse sU)
        float* sp = &sU[0][0];
        #pragma unroll
        for (int j = 0; j < 8; ++j) {
            sp[rg*128 + oc0 + j]        = p[j];
            sp[1024 + rg*128 + oc0 + j] = p2[j];
        }
        __syncthreads();
        {
            float s = 0.f, s2 = 0.f;
            #pragma unroll
            for (int g = 0; g < 8; ++g) { s += sp[g*128 + tid]; s2 += sp[1024 + g*128 + tid]; }
            d_part [blockIdx.x*128 + tid] = s;
            d_part2[blockIdx.x*128 + tid] = s2;
        }
    }
}

// ---------------- BN stats (double accumulation; deterministic) ----------------
__global__ void reduce_kernel(const float* __restrict__ bn_g, const float* __restrict__ bn_b)
{
    int c = threadIdx.x;
    if (c >= 128) return;
    double s = 0.0, s2 = 0.0;
    for (int b = 0; b < NBLK; ++b) { s += (double)d_part[b*128+c]; s2 += (double)d_part2[b*128+c]; }
    double mu  = s  / (double)EE;
    double var = s2 / (double)EE - mu*mu;
    float istd = (float)(1.0 / sqrt(var + 1e-5));
    float al = bn_g[c] * istd;
    d_alpha[c] = al;
    d_beta[c]  = bn_b[c] - (float)mu * al;
}

// ---------------- final: out = fm_w2 @ relu(alpha*z + beta) + fm_b2 ----------------
__global__ __launch_bounds__(256) void final_kernel(const float* __restrict__ fm_w2,
                                                    const float* __restrict__ fm_b2,
                                                    float* __restrict__ out)
{
    __shared__ float sw[3*128];
    __shared__ float sa[128], sb[128];
    __shared__ float sbias[3];
    int tid = threadIdx.x;
    for (int t = tid; t < 384; t += 256) sw[t] = fm_w2[t];
    if (tid < 128) { sa[tid] = d_alpha[tid]; sb[tid] = d_beta[tid]; }
    if (tid < 3)   sbias[tid] = fm_b2[tid];
    __syncthreads();

    int r = tid >> 2, part = tid & 3;
    long e = (long)blockIdx.x * 64 + r;
    long ec = (e < EE) ? e : (EE - 1);
    const float4* zp = (const float4*)(d_z + ec*128) + part*8;
    float a0 = 0.f, a1 = 0.f, a2 = 0.f;
    int base = part * 32;
    #pragma unroll
    for (int i = 0; i < 8; ++i) {
        float4 v = zp[i];
        float vv[4] = {v.x, v.y, v.z, v.w};
        #pragma unroll
        for (int q = 0; q < 4; ++q) {
            int c = base + i*4 + q;
            float zn = fmaxf(fmaf(sa[c], vv[q], sb[c]), 0.f);
            a0 = fmaf(zn, sw[c],       a0);
            a1 = fmaf(zn, sw[128 + c], a1);
            a2 = fmaf(zn, sw[256 + c], a2);
        }
    }
    a0 += __shfl_xor_sync(0xffffffffu, a0, 1); a0 += __shfl_xor_sync(0xffffffffu, a0, 2);
    a1 += __shfl_xor_sync(0xffffffffu, a1, 1); a1 += __shfl_xor_sync(0xffffffffu, a1, 2);
    a2 += __shfl_xor_sync(0xffffffffu, a2, 1); a2 += __shfl_xor_sync(0xffffffffu, a2, 2);
    if (part == 0 && e < EE) {
        out[e*3 + 0] = a0 + sbias[0];
        out[e*3 + 1] = a1 + sbias[1];
        out[e*3 + 2] = a2 + sbias[2];
    }
}

// ---------------- launch ----------------
extern "C" void kernel_launch(void* const* d_in, const int* in_sizes, int n_in,
                              void* d_out, int out_size)
{
    const float* x         = (const float*)d_in[0];
    const void*  eidx      = d_in[1];
    const float* edge_attr = (const float*)d_in[2];
    const float* node_type = (const float*)d_in[4];
    const float* emb       = (const float*)d_in[5];
    const float* conv_w    = (const float*)d_in[6];
    const float* conv_b    = (const float*)d_in[7];
    const float* fuse_w    = (const float*)d_in[8];
    const float* fuse_b    = (const float*)d_in[9];
    const float* g1e_w1    = (const float*)d_in[10];
    const float* g1e_b1    = (const float*)d_in[11];
    const float* g1e_w2    = (const float*)d_in[12];
    const float* g1e_b2    = (const float*)d_in[13];
    const float* g1n_w1    = (const float*)d_in[14];
    const float* g1n_b1    = (const float*)d_in[15];
    const float* g1n_w2    = (const float*)d_in[16];
    const float* g1n_b2    = (const float*)d_in[17];
    const float* g2e_w1    = (const float*)d_in[18];
    const float* g2e_b1    = (const float*)d_in[19];
    const float* g2e_w2    = (const float*)d_in[20];
    const float* g2e_b2    = (const float*)d_in[21];
    /* d_in[22..25] = g2n_* (dead code in reference) */
    const float* fm_w1     = (const float*)d_in[26];
    const float* fm_b1     = (const float*)d_in[27];
    const float* bn_g      = (const float*)d_in[28];
    const float* bn_b      = (const float*)d_in[29];
    const float* fm_w2     = (const float*)d_in[30];
    const float* fm_b2     = (const float*)d_in[31];
    float* out = (float*)d_out;

    prep_kernel<<<1, 128>>>(conv_w, conv_b, emb, fuse_w, fuse_b, eidx);
    transpose_all<<<184, 256>>>(g1e_w1, g1e_w2, g1n_w1, g1n_w2, g2e_w1, g2e_w2, fm_w1);
    node_kernel<<<313, 128>>>(x, node_type);
    edge_mlp_kernel<0><<<NBLK, 128>>>(eidx, edge_attr, g1e_b1, g1e_b2, nullptr, EE);
    edge_mlp_kernel<1><<<313,  128>>>(eidx, edge_attr, g1n_b1, g1n_b2, nullptr, NN);
    edge_mlp_kernel<2><<<NBLK, 128>>>(eidx, edge_attr, g2e_b1, g2e_b2, fm_b1, EE);
    reduce_kernel<<<1, 128>>>(bn_g, bn_b);
    final_kernel<<<NBLK, 256>>>(fm_w2, fm_b2, out);
}